// round 6
// baseline (speedup 1.0000x reference)
#include <cuda_runtime.h>
#include <cuda_bf16.h>

#define B_   8
#define N_   1024
#define IN_  512
#define H_   8
#define SUP_ 64
#define BH_  (B_*H_)      // 64
#define ROWS_ (B_*N_)     // 8192

// Scratch (no cudaMalloc allowed)
__device__ float g_inputs[BH_ * N_ * SUP_];   // [bh][n][o]  16.8 MB
__device__ float g_sfc[BH_ * N_];
__device__ float g_tfc[BH_ * N_];

// ---------- f32x2 helpers ----------
__device__ __forceinline__ unsigned long long pack2(float x, float y){
    unsigned long long r;
    asm("mov.b64 %0, {%1, %2};" : "=l"(r) : "f"(x), "f"(y));
    return r;
}
__device__ __forceinline__ void fma2(unsigned long long &d, unsigned long long a, unsigned long long b){
    asm("fma.rn.f32x2 %0, %1, %2, %0;" : "+l"(d) : "l"(a), "l"(b));
}
__device__ __forceinline__ float2 unpack2(unsigned long long v){
    float2 f;
    asm("mov.b64 {%0, %1}, %2;" : "=f"(f.x), "=f"(f.y) : "l"(v));
    return f;
}

// ---------- polynomial exp on the FMA pipe (no MUFU) ----------
__device__ __forceinline__ float fast_exp(float x){
    float t = x * 1.4426950408889634f;       // x * log2(e)
    t = fmaxf(t, -80.0f);                    // safety clamp
    float r = t + 12582912.0f;               // 1.5*2^23 magic: round-to-nearest
    float f = t - (r - 12582912.0f);         // frac in [-0.5, 0.5]
    int   n = __float_as_int(r) - 0x4B400000;
    float p = 1.33335581e-3f;
    p = fmaf(p, f, 9.61812911e-3f);
    p = fmaf(p, f, 5.55041087e-2f);
    p = fmaf(p, f, 2.40226507e-1f);
    p = fmaf(p, f, 6.93147181e-1f);
    p = fmaf(p, f, 1.0f);
    return __int_as_float(__float_as_int(p) + (n << 23));
}

// ============================================================
// Kernel A: per-head projection  inputs[bh][n][o] = X[b,n,:] @ W[h,:,o]
// CTA: 64 rows x 64 cols (one head), K=512, f32x2 accumulators
// ============================================================
__global__ __launch_bounds__(256) void proj_kernel(const float* __restrict__ X,
                                                   const float* __restrict__ W){
    __shared__ __align__(16) float Xs[64 * 36];   // [row][k], stride 36 (16B-aligned rows)
    __shared__ __align__(16) float Ws[32 * 68];   // [k][col], stride 68 (16B-aligned rows)

    const int h   = blockIdx.y;
    const int R0  = blockIdx.x * 64;
    const int tid = threadIdx.x;
    const int tx  = tid & 15, ty = tid >> 4;
    const int c0  = tx * 4,   r0 = ty * 4;

    unsigned long long acc[4][2];
#pragma unroll
    for (int i = 0; i < 4; i++){ acc[i][0] = 0ull; acc[i][1] = 0ull; }

    const float* Wh = W + h * (IN_ * SUP_);

    for (int kt = 0; kt < IN_; kt += 32){
        __syncthreads();
        // X tile: 64 rows x 32 k
        {
            int row = tid >> 3;             // 0..31
            int kk  = (tid & 7) * 4;
#pragma unroll
            for (int p = 0; p < 2; p++){
                float4 v = *(const float4*)(X + (size_t)(R0 + row + p * 32) * IN_ + kt + kk);
                *(float4*)&Xs[(row + p * 32) * 36 + kk] = v;
            }
        }
        // W tile: 32 k x 64 cols
        {
            int kk = tid >> 4;              // 0..15
            int cc = (tid & 15) * 4;
#pragma unroll
            for (int p = 0; p < 2; p++){
                float4 v = *(const float4*)(Wh + (size_t)(kt + kk + p * 16) * SUP_ + cc);
                *(float4*)&Ws[(kk + p * 16) * 68 + cc] = v;
            }
        }
        __syncthreads();
#pragma unroll 8
        for (int k = 0; k < 32; k++){
            ulonglong2 bv = *(const ulonglong2*)&Ws[k * 68 + c0];
#pragma unroll
            for (int i = 0; i < 4; i++){
                float a = Xs[(r0 + i) * 36 + k];
                unsigned long long aa = pack2(a, a);
                fma2(acc[i][0], aa, bv.x);
                fma2(acc[i][1], aa, bv.y);
            }
        }
    }
#pragma unroll
    for (int i = 0; i < 4; i++){
        int R = R0 + r0 + i;
        int b = R >> 10, n = R & 1023;
        float2 lo = unpack2(acc[i][0]);
        float2 hi = unpack2(acc[i][1]);
        float4 v = make_float4(lo.x, lo.y, hi.x, hi.y);
        *(float4*)&g_inputs[((size_t)(b * H_ + h) * N_ + n) * SUP_ + c0] = v;
    }
}

// ============================================================
// Kernel B: s_fc / t_fc  (one warp per (bh,n) row, 64-wide dot)
// ============================================================
__global__ __launch_bounds__(256) void fc_kernel(const float* __restrict__ w1, const float* __restrict__ b1,
                                                 const float* __restrict__ w2, const float* __restrict__ b2){
    int rid  = blockIdx.x * 8 + (threadIdx.x >> 5);   // 0..65535
    int lane = threadIdx.x & 31;
    int h    = (rid >> 10) & 7;
    const float* row = g_inputs + (size_t)rid * 64;
    float v0 = row[lane], v1 = row[lane + 32];
    float d1 = v0 * w1[h * 64 + lane] + v1 * w1[h * 64 + 32 + lane];
    float d2 = v0 * w2[h * 64 + lane] + v1 * w2[h * 64 + 32 + lane];
#pragma unroll
    for (int off = 16; off >= 1; off >>= 1){
        d1 += __shfl_xor_sync(0xffffffffu, d1, off);
        d2 += __shfl_xor_sync(0xffffffffu, d2, off);
    }
    if (lane == 0){
        g_sfc[rid] = d1 + b1[h];
        g_tfc[rid] = d2 + b2[h];
    }
}

// ============================================================
// Kernel C: fused masked-softmax attention + aggregation + relu
// CTA = one (b,h), 64 rows; warp = 8 rows (4 per 16-lane half);
// lane16 owns 4 output cols -> 8 warp-FMA2 per m
// ============================================================
__global__ __launch_bounds__(256) void attn_kernel(const float* __restrict__ A,
                                                   float* __restrict__ out){
    __shared__ __align__(16) float in_s[128 * 64];   // 32 KB tile of inputs[bh]
    __shared__ float t_s[N_];                        // 4 KB

    const int bh  = blockIdx.y;
    const int b   = bh >> 3, h = bh & 7;
    const int tid = threadIdx.x;
    const int w   = tid >> 5, lane = tid & 31;
    const int halfsel = lane & 16;                   // 0 or 16
    const int lane16  = lane & 15;
    const int c0      = lane16 * 4;
    const int rbase   = blockIdx.x * 64 + w * 8 + (halfsel >> 2);  // +4 for upper half

    // stage t_fc for this (b,h)
    {
        const float* tsrc = g_tfc + (size_t)bh * N_;
#pragma unroll
        for (int j = 0; j < 4; j++) t_s[tid + j * 256] = tsrc[tid + j * 256];
    }

    float s[4], lsum[4];
    unsigned long long acc[4][2];
#pragma unroll
    for (int i = 0; i < 4; i++){
        s[i]    = g_sfc[(size_t)bh * N_ + rbase + i];
        lsum[i] = 0.f;
        acc[i][0] = 0ull; acc[i][1] = 0ull;
    }

    const float* inbase = g_inputs + (size_t)bh * (N_ * SUP_);
    const float* Ab     = A + (size_t)b * N_ * N_;

    for (int mt = 0; mt < N_; mt += 128){
        __syncthreads();
        {   // cooperative load of inputs tile (contiguous 32 KB)
            const float4* src = (const float4*)(inbase + (size_t)mt * SUP_);
            float4*       dst = (float4*)in_s;
#pragma unroll
            for (int j = 0; j < 8; j++) dst[tid + j * 256] = src[tid + j * 256];
        }
        __syncthreads();

#pragma unroll 1
        for (int cc = 0; cc < 8; cc++){
            const int m_g = mt + cc * 16 + lane16;
            const float tv = t_s[m_g];
            float er[4];
#pragma unroll
            for (int i = 0; i < 4; i++){
                float a = Ab[(size_t)(rbase + i) * N_ + m_g];   // 0.0 or 1.0
                float l = s[i] + tv;
                l = fmaxf(l, 0.f) + 0.01f * fminf(l, 0.f);      // leaky_relu
                float e = a * fast_exp(l);                      // mask folds to *0
                er[i] = e;
                lsum[i] += e;
            }
#pragma unroll 4
            for (int k = 0; k < 16; k++){
                ulonglong2 x = *(const ulonglong2*)&in_s[(cc * 16 + k) * 64 + c0];
#pragma unroll
                for (int i = 0; i < 4; i++){
                    float e = __shfl_sync(0xffffffffu, er[i], halfsel + k);
                    unsigned long long ee = pack2(e, e);
                    fma2(acc[i][0], ee, x.x);
                    fma2(acc[i][1], ee, x.y);
                }
            }
        }
    }

    // reduce partial softmax denominators across each 16-lane half
#pragma unroll
    for (int i = 0; i < 4; i++){
#pragma unroll
        for (int off = 8; off >= 1; off >>= 1)
            lsum[i] += __shfl_xor_sync(0xffffffffu, lsum[i], off);
    }

#pragma unroll
    for (int i = 0; i < 4; i++){
        float inv = 1.0f / lsum[i];                 // softmax normalize (post-hoc)
        float2 lo = unpack2(acc[i][0]);
        float2 hi = unpack2(acc[i][1]);
        float4 v;
        v.x = fmaxf(lo.x, 0.f) * inv;               // relu(sum)*inv == relu(sum*inv)
        v.y = fmaxf(lo.y, 0.f) * inv;
        v.z = fmaxf(hi.x, 0.f) * inv;
        v.w = fmaxf(hi.y, 0.f) * inv;
        *(float4*)&out[((size_t)(b * N_ + rbase + i)) * (H_ * SUP_) + h * SUP_ + c0] = v;
    }
}

// ============================================================
extern "C" void kernel_launch(void* const* d_in, const int* in_sizes, int n_in,
                              void* d_out, int out_size){
    // Robust input matching by element count (ties resolved in order):
    // A=8388608, X=4194304, W=262144, w1/w2=512, b1/b2=8
    const float *A = nullptr, *X = nullptr, *W = nullptr;
    const float *w1 = nullptr, *w2 = nullptr, *b1 = nullptr, *b2 = nullptr;
    for (int i = 0; i < n_in; i++){
        const float* p = (const float*)d_in[i];
        switch (in_sizes[i]){
            case 8388608: A = p; break;
            case 4194304: X = p; break;
            case 262144:  W = p; break;
            case 512:     (w1 ? w2 : w1) = p; break;
            case 8:       (b1 ? b2 : b1) = p; break;
            default: break;
        }
    }
    float* out = (float*)d_out;

    proj_kernel<<<dim3(ROWS_ / 64, H_), 256>>>(X, W);
    fc_kernel<<<BH_ * N_ / 8, 256>>>(w1, b1, w2, b2);
    attn_kernel<<<dim3(N_ / 64, BH_), 256>>>(A, out);
}